// round 1
// baseline (speedup 1.0000x reference)
#include <cuda_runtime.h>
#include <math_constants.h>

#define B_ 32
#define S_ 2048
#define H_ 1024
#define CHUNKS 16
#define ROWS_PER_CTA (S_ / CHUNKS)   // 128
#define NWARPS 8
#define NTHREADS (NWARPS * 32)       // 256
#define NV4 (H_ / 4)                 // 256 float4 per row

// Scratch for split-S partials (allocation-free: __device__ globals).
__device__ float  g_pm[B_ * CHUNKS];
__device__ float  g_pl[B_ * CHUNKS];
__device__ float4 g_pacc[B_ * CHUNKS * NV4];

// ---------------------------------------------------------------------------
// Pass 1: one CTA per (batch, S-chunk). Single read of encoder data with
// online softmax + fused weighted accumulation.
// ---------------------------------------------------------------------------
__global__ __launch_bounds__(NTHREADS, 2)
void attn_pass1(const float* __restrict__ enc, const float* __restrict__ W)
{
    const int b     = blockIdx.y;
    const int chunk = blockIdx.x;
    const int tid   = threadIdx.x;
    const int warp  = tid >> 5;
    const int lane  = tid & 31;

    // W_enc = W[H:2H]. Cache this warp-lane's 32 coefficients in registers.
    const float4* W4 = reinterpret_cast<const float4*>(W + H_);
    float4 w[8];
#pragma unroll
    for (int k = 0; k < 8; k++) w[k] = __ldg(&W4[k * 32 + lane]);

    const float4* base = reinterpret_cast<const float4*>(enc) +
        ((size_t)b * S_ + (size_t)chunk * ROWS_PER_CTA) * NV4;

    float m = -CUDART_INF_F;
    float l = 0.0f;
    float4 acc[8];
#pragma unroll
    for (int k = 0; k < 8; k++) acc[k] = make_float4(0.f, 0.f, 0.f, 0.f);

    // Each warp processes whole rows: row data lives in registers, used for
    // both the score dot-product and the weighted accumulation (single load).
    for (int r = warp; r < ROWS_PER_CTA; r += NWARPS) {
        const float4* row = base + (size_t)r * NV4;
        float4 v[8];
#pragma unroll
        for (int k = 0; k < 8; k++) v[k] = __ldcs(&row[k * 32 + lane]);

        // score = dot(enc_row, W_enc)   (per-batch constant shift cancels in softmax)
        float s = 0.0f;
#pragma unroll
        for (int k = 0; k < 8; k++) {
            s = fmaf(v[k].x, w[k].x, s);
            s = fmaf(v[k].y, w[k].y, s);
            s = fmaf(v[k].z, w[k].z, s);
            s = fmaf(v[k].w, w[k].w, s);
        }
#pragma unroll
        for (int off = 16; off > 0; off >>= 1)
            s += __shfl_xor_sync(0xffffffffu, s, off);

        // Online softmax update
        float mn    = fmaxf(m, s);
        float scale = __expf(m - mn);     // exp(-inf)=0 handles first iter
        float p     = __expf(s - mn);
        l = l * scale + p;
#pragma unroll
        for (int k = 0; k < 8; k++) {
            acc[k].x = fmaf(acc[k].x, scale, p * v[k].x);
            acc[k].y = fmaf(acc[k].y, scale, p * v[k].y);
            acc[k].z = fmaf(acc[k].z, scale, p * v[k].z);
            acc[k].w = fmaf(acc[k].w, scale, p * v[k].w);
        }
        m = mn;
    }

    // ---- combine the 8 warps' partial states through shared memory ----
    __shared__ float  sm_m[NWARPS];
    __shared__ float  sm_l[NWARPS];
    __shared__ float4 sm_acc[NWARPS * NV4];   // 32 KB

#pragma unroll
    for (int k = 0; k < 8; k++)
        sm_acc[warp * NV4 + k * 32 + lane] = acc[k];
    if (lane == 0) { sm_m[warp] = m; sm_l[warp] = l; }
    __syncthreads();

    float M = -CUDART_INF_F;
#pragma unroll
    for (int ww = 0; ww < NWARPS; ww++) M = fmaxf(M, sm_m[ww]);

    float  L   = 0.0f;
    float4 sum = make_float4(0.f, 0.f, 0.f, 0.f);
#pragma unroll
    for (int ww = 0; ww < NWARPS; ww++) {
        float sc = __expf(sm_m[ww] - M);
        L += sm_l[ww] * sc;
        float4 a = sm_acc[ww * NV4 + tid];
        sum.x = fmaf(a.x, sc, sum.x);
        sum.y = fmaf(a.y, sc, sum.y);
        sum.z = fmaf(a.z, sc, sum.z);
        sum.w = fmaf(a.w, sc, sum.w);
    }

    const int pid = b * CHUNKS + chunk;
    g_pacc[(size_t)pid * NV4 + tid] = sum;
    if (tid == 0) { g_pm[pid] = M; g_pl[pid] = L; }
}

// ---------------------------------------------------------------------------
// Pass 2: one CTA per batch combines CHUNKS partials and normalizes.
// ---------------------------------------------------------------------------
__global__ __launch_bounds__(NTHREADS, 4)
void attn_pass2(float* __restrict__ out)
{
    const int b   = blockIdx.x;
    const int tid = threadIdx.x;

    float M = -CUDART_INF_F;
#pragma unroll
    for (int c = 0; c < CHUNKS; c++)
        M = fmaxf(M, g_pm[b * CHUNKS + c]);

    float  L   = 0.0f;
    float4 sum = make_float4(0.f, 0.f, 0.f, 0.f);
#pragma unroll
    for (int c = 0; c < CHUNKS; c++) {
        const int pid = b * CHUNKS + c;
        float sc = __expf(g_pm[pid] - M);
        L += g_pl[pid] * sc;
        float4 a = g_pacc[(size_t)pid * NV4 + tid];
        sum.x = fmaf(a.x, sc, sum.x);
        sum.y = fmaf(a.y, sc, sum.y);
        sum.z = fmaf(a.z, sc, sum.z);
        sum.w = fmaf(a.w, sc, sum.w);
    }

    float inv = 1.0f / L;
    float4 o  = make_float4(sum.x * inv, sum.y * inv, sum.z * inv, sum.w * inv);
    reinterpret_cast<float4*>(out)[b * NV4 + tid] = o;
}

// ---------------------------------------------------------------------------
// kernel_launch: inputs are [decoder_hidden, encoder_hidden_outputs, W, b].
// decoder_hidden / W_dec / bias shift all scores of a batch by a constant,
// which softmax cancels — so only enc (d_in[1]) and W (d_in[2]) are needed.
// ---------------------------------------------------------------------------
extern "C" void kernel_launch(void* const* d_in, const int* in_sizes, int n_in,
                              void* d_out, int out_size)
{
    const float* enc = (const float*)d_in[1];
    const float* W   = (const float*)d_in[2];
    float* out       = (float*)d_out;

    dim3 grid1(CHUNKS, B_);
    attn_pass1<<<grid1, NTHREADS>>>(enc, W);
    attn_pass2<<<B_, NTHREADS>>>(out);
}